// round 4
// baseline (speedup 1.0000x reference)
#include <cuda_runtime.h>

#define B_WORDS 512
#define M_POS   256
#define KK      26
#define DD      128
#define PADW    27
#define ROWS_TOTAL (B_WORDS * M_POS)
#define OUT_DW  (KK * DD)      // 3328
#define OUT_TOTAL (OUT_DW + KK * KK) // 4004

// Scratch (static __device__ arrays; no runtime allocation)
__device__ float g_es[ROWS_TOTAL * KK];   // exp(scores - rowmax), 13.6 MB
__device__ float g_M [ROWS_TOTAL * KK];   // onehot - p1, 13.6 MB
__device__ float g_eT[704];               // exp(T), padded with zeros

// ---------- packed f32x2 helpers ----------
__device__ __forceinline__ unsigned long long pack2(float lo, float hi) {
    unsigned long long r;
    asm("mov.b64 %0, {%1,%2};" : "=l"(r) : "f"(lo), "f"(hi));
    return r;
}
__device__ __forceinline__ void unpack2(unsigned long long v, float& lo, float& hi) {
    asm("mov.b64 {%0,%1}, %2;" : "=f"(lo), "=f"(hi) : "l"(v));
}
__device__ __forceinline__ void ffma2(unsigned long long& d, unsigned long long a, unsigned long long b) {
    asm("fma.rn.f32x2 %0, %1, %2, %0;" : "+l"(d) : "l"(a), "l"(b));
}

// ---------- kernel 0: zero output, compute exp(T) ----------
__global__ void k0_init(const float* __restrict__ T, float* __restrict__ out) {
    int i = blockIdx.x * blockDim.x + threadIdx.x;
    if (i < OUT_TOTAL) out[i] = 0.0f;
    if (i < KK * KK)       g_eT[i] = __expf(T[i]);
    else if (i < 704)      g_eT[i] = 0.0f;
}

// ---------- kernel 1: scores = X @ W^T, es = exp(scores - rowmax) ----------
// Register-blocked: thread = (row pair {i, i+128}, k-half). 256 rows/block.
// sW transposed [d][28] so both k-halves load from distinct banks (dual broadcast).
__global__ void __launch_bounds__(256) k1_scores(const float* __restrict__ X,
                                                 const float* __restrict__ Wg) {
    __shared__ float sX[256 * 33];   // 33792 B, rows x 32-d chunk (pad 33)
    __shared__ float sW[128 * 28];   // 14336 B, W transposed [d][k], pad 28

    const int t  = threadIdx.x;
    const int kh = t & 1;            // k-half: 0 -> k 0..12, 1 -> k 13..25
    const int i  = t >> 1;           // row-pair index 0..127
    const size_t base = (size_t)blockIdx.x * 256;

    // stage W transposed (once)
    for (int e = t; e < KK * DD; e += 256) {
        int k = e >> 7, d = e & 127;
        sW[d * 28 + k] = Wg[e];
    }

    float a0[13], a1[13];
#pragma unroll
    for (int k = 0; k < 13; k++) { a0[k] = 0.0f; a1[k] = 0.0f; }

    for (int dc = 0; dc < 4; dc++) {
        __syncthreads();
        // stage 256 rows x 32 d's, coalesced
        for (int e = t; e < 8192; e += 256) {
            int r = e >> 5, s = e & 31;
            sX[r * 33 + s] = X[(base + r) * DD + dc * 32 + s];
        }
        __syncthreads();
        const float* xr0 = sX + i * 33;
        const float* xr1 = sX + (i + 128) * 33;
        const float* wb  = sW + (dc * 32) * 28 + kh * 13;
#pragma unroll 4
        for (int s = 0; s < 32; s++) {
            float x0 = xr0[s], x1 = xr1[s];
            const float* wp = wb + s * 28;
#pragma unroll
            for (int k = 0; k < 13; k++) {
                float w = wp[k];
                a0[k] = fmaf(x0, w, a0[k]);
                a1[k] = fmaf(x1, w, a1[k]);
            }
        }
    }

    // row max across the two k-halves (partner lane = t^1, same warp)
    float m0 = a0[0], m1 = a1[0];
#pragma unroll
    for (int k = 1; k < 13; k++) { m0 = fmaxf(m0, a0[k]); m1 = fmaxf(m1, a1[k]); }
    m0 = fmaxf(m0, __shfl_xor_sync(0xffffffffu, m0, 1));
    m1 = fmaxf(m1, __shfl_xor_sync(0xffffffffu, m1, 1));

    float* e0 = g_es + (base + i) * (size_t)KK + kh * 13;
    float* e1 = g_es + (base + i + 128) * (size_t)KK + kh * 13;
#pragma unroll
    for (int k = 0; k < 13; k++) {
        e0[k] = __expf(a0[k] - m0);
        e1[k] = __expf(a1[k] - m1);
    }
}

// ---------- kernel 2: per-word recursions + p1/p2 marginals -> M, dT ----------
// smem layout (floats): sA[256*27+8] | sB[256*27+8] | sT[704] | sb0[32] | sdT[676] | slab[256]
#define SM_A   0
#define SM_B   (M_POS * PADW + 8)
#define SM_T   (2 * (M_POS * PADW + 8))
#define SM_B0  (SM_T + 704)
#define SM_DT  (SM_B0 + 32)
#define SM_LAB (SM_DT + KK * KK)
#define SMEM2_WORDS (SM_LAB + M_POS)
#define SMEM2_BYTES (SMEM2_WORDS * 4)

__global__ void __launch_bounds__(256, 3) k2_recursion(const int* __restrict__ labels,
                                                       float* __restrict__ out) {
    extern __shared__ float sm[];
    float* sA  = sm + SM_A;
    float* sB  = sm + SM_B;
    float* sT  = sm + SM_T;
    float* sb0 = sm + SM_B0;
    float* sdT = sm + SM_DT;
    int*   slab = (int*)(sm + SM_LAB);

    const int w = blockIdx.x;
    const int tid = threadIdx.x;

    // ---- phase A: stage es into BOTH buffers (A and Bt start as es), eT, labels ----
    const float* es = g_es + (size_t)w * (M_POS * KK);
    for (int idx = tid; idx < M_POS * PADW; idx += 256) {
        int r = idx / PADW, c = idx - r * PADW;
        float v = (c < KK) ? es[r * KK + c] : 0.0f;
        sA[idx] = v; sB[idx] = v;
    }
    if (tid < 8) { sA[M_POS * PADW + tid] = 0.0f; sB[M_POS * PADW + tid] = 0.0f; }
    for (int idx = tid; idx < 704; idx += 256) sT[idx] = g_eT[idx];
    for (int idx = tid; idx < KK * KK; idx += 256) sdT[idx] = 0.0f;
    for (int idx = tid; idx < M_POS; idx += 256) slab[idx] = labels[(size_t)w * M_POS + idx];
    if (tid < 32) sb0[tid] = 0.0f;
    __syncthreads();

    const int warp = tid >> 5, lane = tid & 31;

    // ---- phase B: serial recursions (warp 0 forward, warp 1 backward) ----
    if (warp == 0) {
        // lane y holds eT[:, y]
        float eTc[KK];
#pragma unroll
        for (int j = 0; j < KK; j++) eTc[j] = sT[j * KK + lane];
        for (int i = 1; i < M_POS; i++) {
            const float* prev = sA + (i - 1) * PADW;
            float v0 = 0.f, v1 = 0.f, v2 = 0.f, v3 = 0.f;
#pragma unroll
            for (int j = 0; j < 24; j += 4) {
                v0 = fmaf(prev[j],     eTc[j],     v0);
                v1 = fmaf(prev[j + 1], eTc[j + 1], v1);
                v2 = fmaf(prev[j + 2], eTc[j + 2], v2);
                v3 = fmaf(prev[j + 3], eTc[j + 3], v3);
            }
            v0 = fmaf(prev[24], eTc[24], v0);
            v1 = fmaf(prev[25], eTc[25], v1);
            float v  = (v0 + v1) + (v2 + v3);         // atilde[i]
            float nw = v * sA[i * PADW + lane];       // * es[i] -> A[i]
            if ((i & 7) == 0) {                       // periodic rescale by row max
                float tmx = (lane < KK) ? nw : 0.0f;
#pragma unroll
                for (int o = 16; o; o >>= 1) tmx = fmaxf(tmx, __shfl_xor_sync(0xffffffffu, tmx, o));
                float sc = (tmx > 0.0f) ? __fdividef(1.0f, tmx) : 1.0f;
                nw *= sc;
            }
            if (lane < KK) sA[i * PADW + lane] = nw;
            __syncwarp();
        }
    } else if (warp == 1) {
        // lane y holds eT[y, :]
        int ll = (lane < KK) ? lane : 0;
        float eTr[KK];
#pragma unroll
        for (int j = 0; j < KK; j++) eTr[j] = sT[ll * KK + j];
        for (int i = M_POS - 2; i >= 0; i--) {
            const float* nxt = sB + (i + 1) * PADW;
            float v0 = 0.f, v1 = 0.f, v2 = 0.f, v3 = 0.f;
#pragma unroll
            for (int j = 0; j < 24; j += 4) {
                v0 = fmaf(nxt[j],     eTr[j],     v0);
                v1 = fmaf(nxt[j + 1], eTr[j + 1], v1);
                v2 = fmaf(nxt[j + 2], eTr[j + 2], v2);
                v3 = fmaf(nxt[j + 3], eTr[j + 3], v3);
            }
            v0 = fmaf(nxt[24], eTr[24], v0);
            v1 = fmaf(nxt[25], eTr[25], v1);
            float v = (v0 + v1) + (v2 + v3);          // btilde[i]
            if (i == 0 && lane < KK) sb0[lane] = v;   // saved for p1[0]
            float nw = v * sB[i * PADW + lane];       // * es[i] -> Bt[i]
            if ((i & 7) == 0) {
                float tmx = (lane < KK) ? nw : 0.0f;
#pragma unroll
                for (int o = 16; o; o >>= 1) tmx = fmaxf(tmx, __shfl_xor_sync(0xffffffffu, tmx, o));
                float sc = (tmx > 0.0f) ? __fdividef(1.0f, tmx) : 1.0f;
                nw *= sc;
            }
            if (lane < KK) sB[i * PADW + lane] = nw;
            __syncwarp();
        }
    }
    __syncthreads();

    // ---- phase C: marginals. lane = b. p2[i,a,b] = A[i,a]*eT[a,b]*Bt[i+1,b]/S_i ----
    float* Mw = g_M + (size_t)w * (M_POS * KK);

    if (warp == 0) {  // p1[0] ~ A[0,k] * btilde0[k]
        float tv = (lane < KK) ? sA[lane] * sb0[lane] : 0.0f;
        float s = tv;
#pragma unroll
        for (int o = 16; o; o >>= 1) s += __shfl_xor_sync(0xffffffffu, s, o);
        float p = tv * __fdividef(1.0f, s);
        if (lane < KK) Mw[lane] = ((slab[0] == lane) ? 1.0f : 0.0f) - p;
    }

    float eTc[KK];   // eT[a, lane]
#pragma unroll
    for (int a = 0; a < KK; a++) eTc[a] = sT[a * KK + lane];
    float ga[KK];    // Sum_i A[i,a] * f_i   (f = Bt[i+1,b]*invS)
#pragma unroll
    for (int a = 0; a < KK; a++) ga[a] = 0.0f;

    for (int i = warp; i < M_POS - 1; i += 8) {
        const float* Ar = sA + i * PADW;
        float wb = sB[(i + 1) * PADW + lane];
        float s0 = 0.f, s1 = 0.f;
#pragma unroll
        for (int a = 0; a < KK; a += 2) {
            s0 = fmaf(Ar[a],     eTc[a],     s0);
            s1 = fmaf(Ar[a + 1], eTc[a + 1], s1);
        }
        float sb = s0 + s1;                       // Sum_a A[i,a] eT[a,b]
        float contrib = (lane < KK) ? sb * wb : 0.0f;
        float S = contrib;
#pragma unroll
        for (int o = 16; o; o >>= 1) S += __shfl_xor_sync(0xffffffffu, S, o);
        float invS = __fdividef(1.0f, S);
        float f = wb * invS;
#pragma unroll
        for (int a = 0; a < KK; a++) ga[a] = fmaf(Ar[a], f, ga[a]);
        // p1[i+1, b] = sb * f  (column-marginal of p2)
        int y1 = slab[i + 1];
        if (lane < KK) {
            float p = sb * f;
            Mw[(i + 1) * KK + lane] = ((y1 == lane) ? 1.0f : 0.0f) - p;
        }
        if (lane == 0) atomicAdd(&sdT[slab[i] * KK + y1], 1.0f);  // empirical pair count
    }
    // dT[a,b] -= eT[a,b] * ga[a]
#pragma unroll
    for (int a = 0; a < KK; a++)
        if (lane < KK) atomicAdd(&sdT[a * KK + lane], -eTc[a] * ga[a]);
    __syncthreads();

    const float invB = 1.0f / (float)B_WORDS;
    for (int idx = tid; idx < KK * KK; idx += 256)
        atomicAdd(out + OUT_DW + idx, sdT[idx] * invB);
}

// ---------- kernel 3: dw = M^T @ X (mean over words) ----------
// 256 threads: thread = (kh = t>>7, row-quarter = (t>>5)&3, d-group = t&31 [4 floats]).
// Per row: 13 broadcast LDS.32 (m) + 1 LDS.128 (x) = 17 crossbar-cyc serving 26 FFMA2.
__global__ void __launch_bounds__(256) k3_dw(const float* __restrict__ X,
                                             float* __restrict__ out) {
    __shared__ float sX[64 * 132];   // 33792 B (pad 132, 16B-aligned rows)
    __shared__ float sM[64 * 27];    //  6912 B

    const int t   = threadIdx.x;
    const int dpg = t & 31;          // d-group: floats 4*dpg .. 4*dpg+3
    const int rq  = (t >> 5) & 3;    // row quarter within 64-row chunk
    const int kh  = t >> 7;          // k-half (warp-uniform)

    unsigned long long acc0[13], acc1[13];
#pragma unroll
    for (int k = 0; k < 13; k++) { acc0[k] = 0ull; acc1[k] = 0ull; }

    const size_t rbase0 = (size_t)blockIdx.x * 512;

    for (int ch = 0; ch < 8; ch++) {
        const size_t rb = rbase0 + ch * 64;
        __syncthreads();
        // stage X chunk: 64 rows x 128 floats (coalesced float4)
        for (int e = t; e < 2048; e += 256) {
            int r = e >> 5, q4 = e & 31;
            float4 v = ((const float4*)(X + (rb + r) * DD))[q4];
            *(float4*)&sX[r * 132 + q4 * 4] = v;
        }
        // stage M chunk: 64 x 26
        for (int e = t; e < 64 * KK; e += 256) {
            int r = e / KK, k = e - r * KK;
            sM[r * 27 + k] = g_M[(rb + r) * KK + k];
        }
        __syncthreads();
#pragma unroll 2
        for (int rr = 0; rr < 16; rr++) {
            int r = rq * 16 + rr;
            float4 xv = *(const float4*)&sX[r * 132 + dpg * 4];
            unsigned long long xa = pack2(xv.x, xv.y);
            unsigned long long xb = pack2(xv.z, xv.w);
            const float* mp = sM + r * 27 + kh * 13;
#pragma unroll
            for (int k = 0; k < 13; k++) {
                float m = mp[k];
                unsigned long long mm = pack2(m, m);
                ffma2(acc0[k], mm, xa);
                ffma2(acc1[k], mm, xb);
            }
        }
    }

    const float sc = 1.0f / (float)B_WORDS;
#pragma unroll
    for (int k = 0; k < 13; k++) {
        float lo, hi;
        int kg = kh * 13 + k;
        float* o = out + kg * DD + dpg * 4;
        unpack2(acc0[k], lo, hi);
        atomicAdd(o + 0, lo * sc);
        atomicAdd(o + 1, hi * sc);
        unpack2(acc1[k], lo, hi);
        atomicAdd(o + 2, lo * sc);
        atomicAdd(o + 3, hi * sc);
    }
}

// ---------- launch ----------
extern "C" void kernel_launch(void* const* d_in, const int* in_sizes, int n_in,
                              void* d_out, int out_size) {
    const float* data   = (const float*)d_in[0];   // [512,256,128] f32
    const int*   labels = (const int*)d_in[1];     // [512,256] int32
    const float* W      = (const float*)d_in[2];   // [26,128] f32
    const float* T      = (const float*)d_in[3];   // [26,26] f32
    float* out = (float*)d_out;                    // [4004] f32

    cudaFuncSetAttribute(k2_recursion, cudaFuncAttributeMaxDynamicSharedMemorySize, SMEM2_BYTES);

    k0_init<<<16, 256>>>(T, out);
    k1_scores<<<512, 256>>>(data, W);
    k2_recursion<<<512, 256, SMEM2_BYTES>>>(labels, out);
    k3_dw<<<256, 256>>>(data, out);
}

// round 7
// speedup vs baseline: 1.1829x; 1.1829x over previous
#include <cuda_runtime.h>

#define B_WORDS 512
#define M_POS   256
#define KK      26
#define DD      128
#define PADW    27
#define ROWS_TOTAL (B_WORDS * M_POS)
#define OUT_DW  (KK * DD)      // 3328
#define OUT_TOTAL (OUT_DW + KK * KK) // 4004

typedef unsigned long long ull;

// Scratch (static __device__ arrays; no runtime allocation)
__device__ float g_es[ROWS_TOTAL * KK];   // exp(scores - rowmax), 13.6 MB
__device__ float g_M [ROWS_TOTAL * KK];   // onehot - p1, 13.6 MB
__device__ float g_eT[704];               // exp(T), padded with zeros

// ---------- packed f32x2 helpers ----------
__device__ __forceinline__ ull pack2(float lo, float hi) {
    ull r;
    asm("mov.b64 %0, {%1,%2};" : "=l"(r) : "f"(lo), "f"(hi));
    return r;
}
__device__ __forceinline__ void unpack2(ull v, float& lo, float& hi) {
    asm("mov.b64 {%0,%1}, %2;" : "=f"(lo), "=f"(hi) : "l"(v));
}
__device__ __forceinline__ void ffma2(ull& d, ull a, ull b) {
    asm("fma.rn.f32x2 %0, %1, %2, %0;" : "+l"(d) : "l"(a), "l"(b));
}

// ---------- kernel 0: zero output, compute exp(T) ----------
__global__ void k0_init(const float* __restrict__ T, float* __restrict__ out) {
    int i = blockIdx.x * blockDim.x + threadIdx.x;
    if (i < OUT_TOTAL) out[i] = 0.0f;
    if (i < KK * KK)       g_eT[i] = __expf(T[i]);
    else if (i < 704)      g_eT[i] = 0.0f;
}

// ---------- kernel 1: scores = X @ W^T, es = exp(scores - rowmax) ----------
// Dynamic smem: sW2 (ull[64*32], 16384 B) then sX (float[256*34], 34816 B) = 51200 B.
// thread = (row pair {i,i+128}, k-half). Contraction over d in f32x2 pairs.
#define SMEM1_BYTES (64 * 32 * 8 + 256 * 34 * 4)

__global__ void __launch_bounds__(256) k1_scores(const float* __restrict__ X,
                                                 const float* __restrict__ Wg) {
    extern __shared__ ull dyn1[];
    ull*   sW2 = dyn1;                    // [64*32]
    float* sX  = (float*)(dyn1 + 64 * 32); // [256*34]

    const int t  = threadIdx.x;
    const int kh = t & 1;              // k-half
    const int i  = t >> 1;             // row-pair index 0..127
    const size_t base = (size_t)blockIdx.x * 256;

    // stage packed W (once): slots 0..12 = k 0..12, slots 16..28 = k 13..25
    for (int e = t; e < 64 * 32; e += 256) {
        int s2 = e >> 5, slot = e & 31;
        float lo = 0.0f, hi = 0.0f;
        if (slot < 13) {
            lo = Wg[slot * DD + 2 * s2]; hi = Wg[slot * DD + 2 * s2 + 1];
        } else if (slot >= 16 && slot < 29) {
            int k = slot - 3;          // 13..25
            lo = Wg[k * DD + 2 * s2]; hi = Wg[k * DD + 2 * s2 + 1];
        }
        sW2[e] = pack2(lo, hi);
    }

    ull acc0[13], acc1[13];
#pragma unroll
    for (int k = 0; k < 13; k++) { acc0[k] = 0ull; acc1[k] = 0ull; }

    for (int dc = 0; dc < 4; dc++) {
        __syncthreads();
        // stage 256 rows x 32 d's, coalesced
        for (int e = t; e < 8192; e += 256) {
            int r = e >> 5, s = e & 31;
            sX[r * 34 + s] = X[(base + r) * DD + dc * 32 + s];
        }
        __syncthreads();
        const float* xr0 = sX + i * 34;
        const float* xr1 = sX + (i + 128) * 34;
#pragma unroll 4
        for (int s2 = 0; s2 < 16; s2++) {
            ull x0 = *(const ull*)&xr0[2 * s2];
            ull x1 = *(const ull*)&xr1[2 * s2];
            const ull* wp = sW2 + (dc * 16 + s2) * 32 + kh * 16;
#pragma unroll
            for (int j = 0; j < 13; j++) {
                ull wv = wp[j];
                ffma2(acc0[j], x0, wv);
                ffma2(acc1[j], x1, wv);
            }
        }
    }

    // reduce pairs, row max across the two k-halves (partner lane = t^1)
    float sv0[13], sv1[13];
    float m0 = -3.0e38f, m1 = -3.0e38f;
#pragma unroll
    for (int k = 0; k < 13; k++) {
        float lo, hi;
        unpack2(acc0[k], lo, hi); sv0[k] = lo + hi; m0 = fmaxf(m0, sv0[k]);
        unpack2(acc1[k], lo, hi); sv1[k] = lo + hi; m1 = fmaxf(m1, sv1[k]);
    }
    m0 = fmaxf(m0, __shfl_xor_sync(0xffffffffu, m0, 1));
    m1 = fmaxf(m1, __shfl_xor_sync(0xffffffffu, m1, 1));

    float* e0 = g_es + (base + i) * (size_t)KK + kh * 13;
    float* e1 = g_es + (base + i + 128) * (size_t)KK + kh * 13;
#pragma unroll
    for (int k = 0; k < 13; k++) {
        e0[k] = __expf(sv0[k] - m0);
        e1[k] = __expf(sv1[k] - m1);
    }
}

// ---------- kernel 2: per-word recursions + p1/p2 marginals -> M, dT ----------
// smem layout (floats): sA[256*27+8] | sB[256*27+8] | sT[704] | sb0[32] | sdT[676] | slab[256]
#define SM_A   0
#define SM_B   (M_POS * PADW + 8)
#define SM_T   (2 * (M_POS * PADW + 8))
#define SM_B0  (SM_T + 704)
#define SM_DT  (SM_B0 + 32)
#define SM_LAB (SM_DT + KK * KK)
#define SMEM2_WORDS (SM_LAB + M_POS)
#define SMEM2_BYTES (SMEM2_WORDS * 4)

__global__ void __launch_bounds__(256, 3) k2_recursion(const int* __restrict__ labels,
                                                       float* __restrict__ out) {
    extern __shared__ float sm[];
    float* sA  = sm + SM_A;
    float* sB  = sm + SM_B;
    float* sT  = sm + SM_T;
    float* sb0 = sm + SM_B0;
    float* sdT = sm + SM_DT;
    int*   slab = (int*)(sm + SM_LAB);

    const int w = blockIdx.x;
    const int tid = threadIdx.x;

    // ---- phase A: stage es into BOTH buffers (A and Bt start as es), eT, labels ----
    const float* es = g_es + (size_t)w * (M_POS * KK);
    for (int idx = tid; idx < M_POS * PADW; idx += 256) {
        int r = idx / PADW, c = idx - r * PADW;
        float v = (c < KK) ? es[r * KK + c] : 0.0f;
        sA[idx] = v; sB[idx] = v;
    }
    if (tid < 8) { sA[M_POS * PADW + tid] = 0.0f; sB[M_POS * PADW + tid] = 0.0f; }
    for (int idx = tid; idx < 704; idx += 256) sT[idx] = g_eT[idx];
    for (int idx = tid; idx < KK * KK; idx += 256) sdT[idx] = 0.0f;
    for (int idx = tid; idx < M_POS; idx += 256) slab[idx] = labels[(size_t)w * M_POS + idx];
    if (tid < 32) sb0[tid] = 0.0f;
    __syncthreads();

    const int warp = tid >> 5, lane = tid & 31;

    // ---- phase B: serial recursions (warp 0 forward, warp 1 backward) ----
    if (warp == 0) {
        // lane y holds eT[:, y]
        float eTc[KK];
#pragma unroll
        for (int j = 0; j < KK; j++) eTc[j] = sT[j * KK + lane];
        for (int i = 1; i < M_POS; i++) {
            const float* prev = sA + (i - 1) * PADW;
            float v0 = 0.f, v1 = 0.f, v2 = 0.f, v3 = 0.f;
#pragma unroll
            for (int j = 0; j < 24; j += 4) {
                v0 = fmaf(prev[j],     eTc[j],     v0);
                v1 = fmaf(prev[j + 1], eTc[j + 1], v1);
                v2 = fmaf(prev[j + 2], eTc[j + 2], v2);
                v3 = fmaf(prev[j + 3], eTc[j + 3], v3);
            }
            v0 = fmaf(prev[24], eTc[24], v0);
            v1 = fmaf(prev[25], eTc[25], v1);
            float v  = (v0 + v1) + (v2 + v3);         // atilde[i]
            float nw = v * sA[i * PADW + lane];       // * es[i] -> A[i]
            if ((i & 7) == 0) {                       // periodic rescale by row max
                float tmx = (lane < KK) ? nw : 0.0f;
#pragma unroll
                for (int o = 16; o; o >>= 1) tmx = fmaxf(tmx, __shfl_xor_sync(0xffffffffu, tmx, o));
                float sc = (tmx > 0.0f) ? __fdividef(1.0f, tmx) : 1.0f;
                nw *= sc;
            }
            if (lane < KK) sA[i * PADW + lane] = nw;
            __syncwarp();
        }
    } else if (warp == 1) {
        // lane y holds eT[y, :]
        int ll = (lane < KK) ? lane : 0;
        float eTr[KK];
#pragma unroll
        for (int j = 0; j < KK; j++) eTr[j] = sT[ll * KK + j];
        for (int i = M_POS - 2; i >= 0; i--) {
            const float* nxt = sB + (i + 1) * PADW;
            float v0 = 0.f, v1 = 0.f, v2 = 0.f, v3 = 0.f;
#pragma unroll
            for (int j = 0; j < 24; j += 4) {
                v0 = fmaf(nxt[j],     eTr[j],     v0);
                v1 = fmaf(nxt[j + 1], eTr[j + 1], v1);
                v2 = fmaf(nxt[j + 2], eTr[j + 2], v2);
                v3 = fmaf(nxt[j + 3], eTr[j + 3], v3);
            }
            v0 = fmaf(nxt[24], eTr[24], v0);
            v1 = fmaf(nxt[25], eTr[25], v1);
            float v = (v0 + v1) + (v2 + v3);          // btilde[i]
            if (i == 0 && lane < KK) sb0[lane] = v;   // saved for p1[0]
            float nw = v * sB[i * PADW + lane];       // * es[i] -> Bt[i]
            if ((i & 7) == 0) {
                float tmx = (lane < KK) ? nw : 0.0f;
#pragma unroll
                for (int o = 16; o; o >>= 1) tmx = fmaxf(tmx, __shfl_xor_sync(0xffffffffu, tmx, o));
                float sc = (tmx > 0.0f) ? __fdividef(1.0f, tmx) : 1.0f;
                nw *= sc;
            }
            if (lane < KK) sB[i * PADW + lane] = nw;
            __syncwarp();
        }
    }
    __syncthreads();

    // ---- phase C: marginals. lane = b. p2[i,a,b] = A[i,a]*eT[a,b]*Bt[i+1,b]/S_i ----
    float* Mw = g_M + (size_t)w * (M_POS * KK);

    if (warp == 0) {  // p1[0] ~ A[0,k] * btilde0[k]
        float tv = (lane < KK) ? sA[lane] * sb0[lane] : 0.0f;
        float s = tv;
#pragma unroll
        for (int o = 16; o; o >>= 1) s += __shfl_xor_sync(0xffffffffu, s, o);
        float p = tv * __fdividef(1.0f, s);
        if (lane < KK) Mw[lane] = ((slab[0] == lane) ? 1.0f : 0.0f) - p;
    }

    float eTc[KK];   // eT[a, lane]
#pragma unroll
    for (int a = 0; a < KK; a++) eTc[a] = sT[a * KK + lane];
    float ga[KK];    // Sum_i A[i,a] * f_i   (f = Bt[i+1,b]*invS)
#pragma unroll
    for (int a = 0; a < KK; a++) ga[a] = 0.0f;

    for (int i = warp; i < M_POS - 1; i += 8) {
        const float* Ar = sA + i * PADW;
        float wb = sB[(i + 1) * PADW + lane];
        float s0 = 0.f, s1 = 0.f;
#pragma unroll
        for (int a = 0; a < KK; a += 2) {
            s0 = fmaf(Ar[a],     eTc[a],     s0);
            s1 = fmaf(Ar[a + 1], eTc[a + 1], s1);
        }
        float sb = s0 + s1;                       // Sum_a A[i,a] eT[a,b]
        float contrib = (lane < KK) ? sb * wb : 0.0f;
        float S = contrib;
#pragma unroll
        for (int o = 16; o; o >>= 1) S += __shfl_xor_sync(0xffffffffu, S, o);
        float invS = __fdividef(1.0f, S);
        float f = wb * invS;
#pragma unroll
        for (int a = 0; a < KK; a++) ga[a] = fmaf(Ar[a], f, ga[a]);
        // p1[i+1, b] = sb * f  (column-marginal of p2)
        int y1 = slab[i + 1];
        if (lane < KK) {
            float p = sb * f;
            Mw[(i + 1) * KK + lane] = ((y1 == lane) ? 1.0f : 0.0f) - p;
        }
        if (lane == 0) atomicAdd(&sdT[slab[i] * KK + y1], 1.0f);  // empirical pair count
    }
    // dT[a,b] -= eT[a,b] * ga[a]
#pragma unroll
    for (int a = 0; a < KK; a++)
        if (lane < KK) atomicAdd(&sdT[a * KK + lane], -eTc[a] * ga[a]);
    __syncthreads();

    const float invB = 1.0f / (float)B_WORDS;
    for (int idx = tid; idx < KK * KK; idx += 256)
        atomicAdd(out + OUT_DW + idx, sdT[idx] * invB);
}

// ---------- kernel 3: dw = M^T @ X (mean over words) ----------
// Dynamic smem: sM2 (ull[64*32], 16384 B) then sX (float[64*132], 33792 B) = 50176 B.
// 8 warps: warp = k-quad (K padded to 32), lane = 4-float d-group.
#define SMEM3_BYTES (64 * 32 * 8 + 64 * 132 * 4)

__global__ void __launch_bounds__(256) k3_dw(const float* __restrict__ X,
                                             float* __restrict__ out) {
    extern __shared__ ull dyn3[];
    ull*   sM2 = dyn3;                     // [64*32]
    float* sX  = (float*)(dyn3 + 64 * 32); // [64*132]

    const int t    = threadIdx.x;
    const int lane = t & 31;         // d-group
    const int wq   = t >> 5;         // warp = k-quad (k = 4*wq .. 4*wq+3)

    ull acc00 = 0ull, acc01 = 0ull;  // k=4wq+0: (d0,d1), (d2,d3)
    ull acc10 = 0ull, acc11 = 0ull;
    ull acc20 = 0ull, acc21 = 0ull;
    ull acc30 = 0ull, acc31 = 0ull;

    const size_t rbase0 = (size_t)blockIdx.x * 256;

    for (int ch = 0; ch < 4; ch++) {
        const size_t rb = rbase0 + ch * 64;
        __syncthreads();
        // stage X chunk: 64 rows x 128 floats (coalesced float4)
        for (int e = t; e < 2048; e += 256) {
            int r = e >> 5, q4 = e & 31;
            float4 v = ((const float4*)(X + (rb + r) * DD))[q4];
            *(float4*)&sX[r * 132 + q4 * 4] = v;
        }
        // stage M chunk duplicated: 64 rows x 32 k-slots
        for (int e = t; e < 2048; e += 256) {
            int r = e >> 5, k = e & 31;
            float m = (k < KK) ? g_M[(rb + r) * KK + k] : 0.0f;
            sM2[r * 32 + k] = pack2(m, m);
        }
        __syncthreads();
#pragma unroll 4
        for (int r = 0; r < 64; r++) {
            const float* xp = sX + r * 132 + lane * 4;
            ull xa = *(const ull*)(xp);       // (x[d0], x[d1])
            ull xb = *(const ull*)(xp + 2);   // (x[d2], x[d3])
            const ull* mp = sM2 + r * 32 + wq * 4;
            ulonglong2 mv0 = *(const ulonglong2*)(mp);      // m for k+0, k+1
            ulonglong2 mv1 = *(const ulonglong2*)(mp + 2);  // m for k+2, k+3
            ffma2(acc00, mv0.x, xa); ffma2(acc01, mv0.x, xb);
            ffma2(acc10, mv0.y, xa); ffma2(acc11, mv0.y, xb);
            ffma2(acc20, mv1.x, xa); ffma2(acc21, mv1.x, xb);
            ffma2(acc30, mv1.y, xa); ffma2(acc31, mv1.y, xb);
        }
    }

    const float sc = 1.0f / (float)B_WORDS;
    ull a0[4] = {acc00, acc10, acc20, acc30};
    ull a1[4] = {acc01, acc11, acc21, acc31};
#pragma unroll
    for (int j = 0; j < 4; j++) {
        int k = wq * 4 + j;
        if (k < KK) {
            float lo, hi;
            float* o = out + k * DD + lane * 4;
            unpack2(a0[j], lo, hi);
            atomicAdd(o + 0, lo * sc);
            atomicAdd(o + 1, hi * sc);
            unpack2(a1[j], lo, hi);
            atomicAdd(o + 2, lo * sc);
            atomicAdd(o + 3, hi * sc);
        }
    }
}

// ---------- launch ----------
extern "C" void kernel_launch(void* const* d_in, const int* in_sizes, int n_in,
                              void* d_out, int out_size) {
    const float* data   = (const float*)d_in[0];   // [512,256,128] f32
    const int*   labels = (const int*)d_in[1];     // [512,256] int32
    const float* W      = (const float*)d_in[2];   // [26,128] f32
    const float* T      = (const float*)d_in[3];   // [26,26] f32
    float* out = (float*)d_out;                    // [4004] f32

    cudaFuncSetAttribute(k1_scores,    cudaFuncAttributeMaxDynamicSharedMemorySize, SMEM1_BYTES);
    cudaFuncSetAttribute(k2_recursion, cudaFuncAttributeMaxDynamicSharedMemorySize, SMEM2_BYTES);
    cudaFuncSetAttribute(k3_dw,        cudaFuncAttributeMaxDynamicSharedMemorySize, SMEM3_BYTES);

    k0_init<<<16, 256>>>(T, out);
    k1_scores<<<512, 256, SMEM1_BYTES>>>(data, W);
    k2_recursion<<<512, 256, SMEM2_BYTES>>>(labels, out);
    k3_dw<<<512, 256, SMEM3_BYTES>>>(data, out);
}

// round 9
// speedup vs baseline: 1.2685x; 1.0724x over previous
#include <cuda_runtime.h>

#define B_WORDS 512
#define M_POS   256
#define KK      26
#define DD      128
#define PADW    27
#define ROWS_TOTAL (B_WORDS * M_POS)
#define OUT_DW  (KK * DD)      // 3328
#define OUT_TOTAL (OUT_DW + KK * KK) // 4004

typedef unsigned long long ull;

// Scratch (static __device__ arrays; no runtime allocation)
__device__ float g_es[ROWS_TOTAL * KK];   // exp(scores - rowmax), 13.6 MB
__device__ float g_M [ROWS_TOTAL * KK];   // onehot - p1, 13.6 MB
__device__ float g_eT[704];               // exp(T), padded with zeros

// ---------- packed f32x2 helpers ----------
__device__ __forceinline__ ull pack2(float lo, float hi) {
    ull r;
    asm("mov.b64 %0, {%1,%2};" : "=l"(r) : "f"(lo), "f"(hi));
    return r;
}
__device__ __forceinline__ void unpack2(ull v, float& lo, float& hi) {
    asm("mov.b64 {%0,%1}, %2;" : "=f"(lo), "=f"(hi) : "l"(v));
}
__device__ __forceinline__ void ffma2(ull& d, ull a, ull b) {
    asm("fma.rn.f32x2 %0, %1, %2, %0;" : "+l"(d) : "l"(a), "l"(b));
}

// ---------- kernel 0: zero output, compute exp(T) ----------
__global__ void k0_init(const float* __restrict__ T, float* __restrict__ out) {
    int i = blockIdx.x * blockDim.x + threadIdx.x;
    if (i < OUT_TOTAL) out[i] = 0.0f;
    if (i < KK * KK)       g_eT[i] = __expf(T[i]);
    else if (i < 704)      g_eT[i] = 0.0f;
}

// ---------- kernel 1: scores = X @ W^T, es = exp(scores - rowmax) ----------
// Dynamic smem: sW2 (ull[64*28], 14336 B) then sX (float[256*34], 34816 B) = 49152 B.
// thread = (row pair {i,i+128}, k-half). Contraction over d in f32x2 pairs.
// sW2 row (per d-pair) = 28 ull slots: k 0..12 at slots 0..12, k 13..25 at 14..26.
// kh offset 14 ull = 28 words (≠0 mod 32) -> the two kh broadcast addrs never collide.
#define SMEM1_BYTES (64 * 28 * 8 + 256 * 34 * 4)

__global__ void __launch_bounds__(256) k1_scores(const float* __restrict__ X,
                                                 const float* __restrict__ Wg) {
    extern __shared__ ull dyn1[];
    ull*   sW2 = dyn1;                     // [64*28]
    float* sX  = (float*)(dyn1 + 64 * 28); // [256*34]

    const int t  = threadIdx.x;
    const int kh = t & 1;              // k-half
    const int i  = t >> 1;             // row-pair index 0..127
    const size_t base = (size_t)blockIdx.x * 256;

    // stage packed W (once)
    for (int e = t; e < 64 * 28; e += 256) {
        int s2 = e / 28, slot = e - s2 * 28;
        float lo = 0.0f, hi = 0.0f;
        int k = -1;
        if (slot < 13) k = slot;
        else if (slot >= 14 && slot < 27) k = slot - 1;
        if (k >= 0) { lo = Wg[k * DD + 2 * s2]; hi = Wg[k * DD + 2 * s2 + 1]; }
        sW2[e] = pack2(lo, hi);
    }

    ull acc0[13], acc1[13];
#pragma unroll
    for (int k = 0; k < 13; k++) { acc0[k] = 0ull; acc1[k] = 0ull; }

    for (int dc = 0; dc < 4; dc++) {
        __syncthreads();
        // stage 256 rows x 32 d's, coalesced
        for (int e = t; e < 8192; e += 256) {
            int r = e >> 5, s = e & 31;
            sX[r * 34 + s] = X[(base + r) * DD + dc * 32 + s];
        }
        __syncthreads();
        const float* xr0 = sX + i * 34;
        const float* xr1 = sX + (i + 128) * 34;
#pragma unroll 4
        for (int s2 = 0; s2 < 16; s2++) {
            ull x0 = *(const ull*)&xr0[2 * s2];
            ull x1 = *(const ull*)&xr1[2 * s2];
            const ull* wp = sW2 + (dc * 16 + s2) * 28 + kh * 14;
            ull wv[13];
            ulonglong2 q;
            q = ((const ulonglong2*)wp)[0]; wv[0] = q.x;  wv[1] = q.y;
            q = ((const ulonglong2*)wp)[1]; wv[2] = q.x;  wv[3] = q.y;
            q = ((const ulonglong2*)wp)[2]; wv[4] = q.x;  wv[5] = q.y;
            q = ((const ulonglong2*)wp)[3]; wv[6] = q.x;  wv[7] = q.y;
            q = ((const ulonglong2*)wp)[4]; wv[8] = q.x;  wv[9] = q.y;
            q = ((const ulonglong2*)wp)[5]; wv[10] = q.x; wv[11] = q.y;
            wv[12] = wp[12];
#pragma unroll
            for (int j = 0; j < 13; j++) {
                ffma2(acc0[j], x0, wv[j]);
                ffma2(acc1[j], x1, wv[j]);
            }
        }
    }

    // reduce pairs, row max across the two k-halves (partner lane = t^1)
    float sv0[13], sv1[13];
    float m0 = -3.0e38f, m1 = -3.0e38f;
#pragma unroll
    for (int k = 0; k < 13; k++) {
        float lo, hi;
        unpack2(acc0[k], lo, hi); sv0[k] = lo + hi; m0 = fmaxf(m0, sv0[k]);
        unpack2(acc1[k], lo, hi); sv1[k] = lo + hi; m1 = fmaxf(m1, sv1[k]);
    }
    m0 = fmaxf(m0, __shfl_xor_sync(0xffffffffu, m0, 1));
    m1 = fmaxf(m1, __shfl_xor_sync(0xffffffffu, m1, 1));

    float* e0 = g_es + (base + i) * (size_t)KK + kh * 13;
    float* e1 = g_es + (base + i + 128) * (size_t)KK + kh * 13;
#pragma unroll
    for (int k = 0; k < 13; k++) {
        e0[k] = __expf(sv0[k] - m0);
        e1[k] = __expf(sv1[k] - m1);
    }
}

// ---------- kernel 2: per-word recursions + p1/p2 marginals -> M, dT ----------
// smem layout (floats): sA[256*27+8] | sB[256*27+8] | sT[704] | sb0[32] | sdT[676] | slab[256]
#define SM_A   0
#define SM_B   (M_POS * PADW + 8)
#define SM_T   (2 * (M_POS * PADW + 8))
#define SM_B0  (SM_T + 704)
#define SM_DT  (SM_B0 + 32)
#define SM_LAB (SM_DT + KK * KK)
#define SMEM2_WORDS (SM_LAB + M_POS)
#define SMEM2_BYTES (SMEM2_WORDS * 4)

__global__ void __launch_bounds__(256, 3) k2_recursion(const int* __restrict__ labels,
                                                       float* __restrict__ out) {
    extern __shared__ float sm[];
    float* sA  = sm + SM_A;
    float* sB  = sm + SM_B;
    float* sT  = sm + SM_T;
    float* sb0 = sm + SM_B0;
    float* sdT = sm + SM_DT;
    int*   slab = (int*)(sm + SM_LAB);

    const int w = blockIdx.x;
    const int tid = threadIdx.x;

    // ---- phase A: stage es into BOTH buffers (A and Bt start as es), eT, labels ----
    const float* es = g_es + (size_t)w * (M_POS * KK);
    for (int idx = tid; idx < M_POS * PADW; idx += 256) {
        int r = idx / PADW, c = idx - r * PADW;
        float v = (c < KK) ? es[r * KK + c] : 0.0f;
        sA[idx] = v; sB[idx] = v;
    }
    if (tid < 8) { sA[M_POS * PADW + tid] = 0.0f; sB[M_POS * PADW + tid] = 0.0f; }
    for (int idx = tid; idx < 704; idx += 256) sT[idx] = g_eT[idx];
    for (int idx = tid; idx < KK * KK; idx += 256) sdT[idx] = 0.0f;
    for (int idx = tid; idx < M_POS; idx += 256) slab[idx] = labels[(size_t)w * M_POS + idx];
    if (tid < 32) sb0[tid] = 0.0f;
    __syncthreads();

    const int warp = tid >> 5, lane = tid & 31;

    // ---- phase B: serial recursions (warp 0 forward, warp 1 backward) ----
    if (warp == 0) {
        // lane y holds eT[:, y]
        float eTc[KK];
#pragma unroll
        for (int j = 0; j < KK; j++) eTc[j] = sT[j * KK + lane];
        for (int i = 1; i < M_POS; i++) {
            const float* prev = sA + (i - 1) * PADW;
            float v0 = 0.f, v1 = 0.f, v2 = 0.f, v3 = 0.f;
#pragma unroll
            for (int j = 0; j < 24; j += 4) {
                v0 = fmaf(prev[j],     eTc[j],     v0);
                v1 = fmaf(prev[j + 1], eTc[j + 1], v1);
                v2 = fmaf(prev[j + 2], eTc[j + 2], v2);
                v3 = fmaf(prev[j + 3], eTc[j + 3], v3);
            }
            v0 = fmaf(prev[24], eTc[24], v0);
            v1 = fmaf(prev[25], eTc[25], v1);
            float v  = (v0 + v1) + (v2 + v3);         // atilde[i]
            float nw = v * sA[i * PADW + lane];       // * es[i] -> A[i]
            if ((i & 7) == 0) {                       // periodic rescale by row max
                float tmx = (lane < KK) ? nw : 0.0f;
#pragma unroll
                for (int o = 16; o; o >>= 1) tmx = fmaxf(tmx, __shfl_xor_sync(0xffffffffu, tmx, o));
                float sc = (tmx > 0.0f) ? __fdividef(1.0f, tmx) : 1.0f;
                nw *= sc;
            }
            if (lane < KK) sA[i * PADW + lane] = nw;
            __syncwarp();
        }
    } else if (warp == 1) {
        // lane y holds eT[y, :]
        int ll = (lane < KK) ? lane : 0;
        float eTr[KK];
#pragma unroll
        for (int j = 0; j < KK; j++) eTr[j] = sT[ll * KK + j];
        for (int i = M_POS - 2; i >= 0; i--) {
            const float* nxt = sB + (i + 1) * PADW;
            float v0 = 0.f, v1 = 0.f, v2 = 0.f, v3 = 0.f;
#pragma unroll
            for (int j = 0; j < 24; j += 4) {
                v0 = fmaf(nxt[j],     eTr[j],     v0);
                v1 = fmaf(nxt[j + 1], eTr[j + 1], v1);
                v2 = fmaf(nxt[j + 2], eTr[j + 2], v2);
                v3 = fmaf(nxt[j + 3], eTr[j + 3], v3);
            }
            v0 = fmaf(nxt[24], eTr[24], v0);
            v1 = fmaf(nxt[25], eTr[25], v1);
            float v = (v0 + v1) + (v2 + v3);          // btilde[i]
            if (i == 0 && lane < KK) sb0[lane] = v;   // saved for p1[0]
            float nw = v * sB[i * PADW + lane];       // * es[i] -> Bt[i]
            if ((i & 7) == 0) {
                float tmx = (lane < KK) ? nw : 0.0f;
#pragma unroll
                for (int o = 16; o; o >>= 1) tmx = fmaxf(tmx, __shfl_xor_sync(0xffffffffu, tmx, o));
                float sc = (tmx > 0.0f) ? __fdividef(1.0f, tmx) : 1.0f;
                nw *= sc;
            }
            if (lane < KK) sB[i * PADW + lane] = nw;
            __syncwarp();
        }
    }
    __syncthreads();

    // ---- phase C: marginals. lane = b. p2[i,a,b] = A[i,a]*eT[a,b]*Bt[i+1,b]/S_i ----
    float* Mw = g_M + (size_t)w * (M_POS * KK);

    if (warp == 0) {  // p1[0] ~ A[0,k] * btilde0[k]
        float tv = (lane < KK) ? sA[lane] * sb0[lane] : 0.0f;
        float s = tv;
#pragma unroll
        for (int o = 16; o; o >>= 1) s += __shfl_xor_sync(0xffffffffu, s, o);
        float p = tv * __fdividef(1.0f, s);
        if (lane < KK) Mw[lane] = ((slab[0] == lane) ? 1.0f : 0.0f) - p;
    }

    float eTc[KK];   // eT[a, lane]
#pragma unroll
    for (int a = 0; a < KK; a++) eTc[a] = sT[a * KK + lane];
    float ga[KK];    // Sum_i A[i,a] * f_i   (f = Bt[i+1,b]*invS)
#pragma unroll
    for (int a = 0; a < KK; a++) ga[a] = 0.0f;

    for (int i = warp; i < M_POS - 1; i += 8) {
        const float* Ar = sA + i * PADW;
        float wb = sB[(i + 1) * PADW + lane];
        float s0 = 0.f, s1 = 0.f;
#pragma unroll
        for (int a = 0; a < KK; a += 2) {
            s0 = fmaf(Ar[a],     eTc[a],     s0);
            s1 = fmaf(Ar[a + 1], eTc[a + 1], s1);
        }
        float sb = s0 + s1;                       // Sum_a A[i,a] eT[a,b]
        float contrib = (lane < KK) ? sb * wb : 0.0f;
        float S = contrib;
#pragma unroll
        for (int o = 16; o; o >>= 1) S += __shfl_xor_sync(0xffffffffu, S, o);
        float invS = __fdividef(1.0f, S);
        float f = wb * invS;
#pragma unroll
        for (int a = 0; a < KK; a++) ga[a] = fmaf(Ar[a], f, ga[a]);
        // p1[i+1, b] = sb * f  (column-marginal of p2)
        int y1 = slab[i + 1];
        if (lane < KK) {
            float p = sb * f;
            Mw[(i + 1) * KK + lane] = ((y1 == lane) ? 1.0f : 0.0f) - p;
        }
        if (lane == 0) atomicAdd(&sdT[slab[i] * KK + y1], 1.0f);  // empirical pair count
    }
    // dT[a,b] -= eT[a,b] * ga[a]
#pragma unroll
    for (int a = 0; a < KK; a++)
        if (lane < KK) atomicAdd(&sdT[a * KK + lane], -eTc[a] * ga[a]);
    __syncthreads();

    const float invB = 1.0f / (float)B_WORDS;
    for (int idx = tid; idx < KK * KK; idx += 256)
        atomicAdd(out + OUT_DW + idx, sdT[idx] * invB);
}

// ---------- kernel 3: dw = M^T @ X (mean over words) ----------
// Dynamic smem: sX (float[64*132], 33792 B) then sM2 (ull[64*28], 14336 B) = 48128 B.
// 8 warps = (kh in {0,1}) x (rh in 0..3). Warp covers 13 k x full 128 d x 16 rows/chunk.
// lane d-segments: a = lane*2, b = 64 + lane*2 (8B stride, conflict-free).
// m pre-duplicated ull, kh halves 14 slots apart (28 words, !=0 mod 32).
#define SMEM3_BYTES (64 * 132 * 4 + 64 * 28 * 8)

__global__ void __launch_bounds__(256) k3_dw(const float* __restrict__ X,
                                             float* __restrict__ out) {
    extern __shared__ float dyn3[];
    float* sX  = dyn3;                      // [64*132]
    ull*   sM2 = (ull*)(dyn3 + 64 * 132);   // [64*28]

    const int t    = threadIdx.x;
    const int lane = t & 31;
    const int wrp  = t >> 5;
    const int kh   = wrp & 1;        // k-half (warp-uniform)
    const int rh   = wrp >> 1;       // row quarter (warp-uniform)

    ull accA[13], accB[13];
#pragma unroll
    for (int j = 0; j < 13; j++) { accA[j] = 0ull; accB[j] = 0ull; }

    const size_t rbase0 = (size_t)blockIdx.x * 256;

    for (int ch = 0; ch < 4; ch++) {
        const size_t rb = rbase0 + ch * 64;
        __syncthreads();
        // stage X chunk: 64 rows x 128 floats (coalesced float4)
        for (int e = t; e < 2048; e += 256) {
            int r = e >> 5, q4 = e & 31;
            float4 v = ((const float4*)(X + (rb + r) * DD))[q4];
            *(float4*)&sX[r * 132 + q4 * 4] = v;
        }
        // stage M chunk as duplicated ull: 64 rows x 28 slots (0..12 -> k0..12, 14..26 -> k13..25)
        for (int e = t; e < 64 * 28; e += 256) {
            int r = e / 28, slot = e - r * 28;
            int k = -1;
            if (slot < 13) k = slot;
            else if (slot >= 14 && slot < 27) k = slot - 1;
            float m = (k >= 0) ? g_M[(rb + r) * KK + k] : 0.0f;
            sM2[e] = pack2(m, m);
        }
        __syncthreads();
#pragma unroll 2
        for (int rr = 0; rr < 16; rr++) {
            int r = rh * 16 + rr;
            const float* xp = sX + r * 132;
            ull xa = *(const ull*)&xp[lane * 2];        // d lane*2, lane*2+1
            ull xb = *(const ull*)&xp[64 + lane * 2];   // d 64+lane*2, +1
            const ull* mp = sM2 + r * 28 + kh * 14;
            ull mv[13];
            ulonglong2 q;
            q = ((const ulonglong2*)mp)[0]; mv[0] = q.x;  mv[1] = q.y;
            q = ((const ulonglong2*)mp)[1]; mv[2] = q.x;  mv[3] = q.y;
            q = ((const ulonglong2*)mp)[2]; mv[4] = q.x;  mv[5] = q.y;
            q = ((const ulonglong2*)mp)[3]; mv[6] = q.x;  mv[7] = q.y;
            q = ((const ulonglong2*)mp)[4]; mv[8] = q.x;  mv[9] = q.y;
            q = ((const ulonglong2*)mp)[5]; mv[10] = q.x; mv[11] = q.y;
            mv[12] = mp[12];
#pragma unroll
            for (int j = 0; j < 13; j++) {
                ffma2(accA[j], mv[j], xa);
                ffma2(accB[j], mv[j], xb);
            }
        }
    }

    // ---- merge the 4 rh partials in smem (ordered passes), then global atomics ----
    __syncthreads();
    float* dwS = dyn3;   // 3328 floats, layout [k(26)][d(128)]
    for (int p = 0; p < 4; p++) {
        if (rh == p) {
#pragma unroll
            for (int j = 0; j < 13; j++) {
                int k = kh * 13 + j;
                float* o = dwS + k * 128;
                float loA, hiA, loB, hiB;
                unpack2(accA[j], loA, hiA);
                unpack2(accB[j], loB, hiB);
                if (p == 0) {
                    o[lane * 2]          = loA;
                    o[lane * 2 + 1]      = hiA;
                    o[64 + lane * 2]     = loB;
                    o[64 + lane * 2 + 1] = hiB;
                } else {
                    o[lane * 2]          += loA;
                    o[lane * 2 + 1]      += hiA;
                    o[64 + lane * 2]     += loB;
                    o[64 + lane * 2 + 1] += hiB;
                }
            }
        }
        __syncthreads();
    }

    const float sc = 1.0f / (float)B_WORDS;
    for (int i = t; i < OUT_DW; i += 256)
        atomicAdd(out + i, dwS[i] * sc);
}

// ---------- launch ----------
extern "C" void kernel_launch(void* const* d_in, const int* in_sizes, int n_in,
                              void* d_out, int out_size) {
    const float* data   = (const float*)d_in[0];   // [512,256,128] f32
    const int*   labels = (const int*)d_in[1];     // [512,256] int32
    const float* W      = (const float*)d_in[2];   // [26,128] f32
    const float* T      = (const float*)d_in[3];   // [26,26] f32
    float* out = (float*)d_out;                    // [4004] f32

    cudaFuncSetAttribute(k1_scores,    cudaFuncAttributeMaxDynamicSharedMemorySize, SMEM1_BYTES);
    cudaFuncSetAttribute(k2_recursion, cudaFuncAttributeMaxDynamicSharedMemorySize, SMEM2_BYTES);
    cudaFuncSetAttribute(k3_dw,        cudaFuncAttributeMaxDynamicSharedMemorySize, SMEM3_BYTES);

    k0_init<<<16, 256>>>(T, out);
    k1_scores<<<512, 256, SMEM1_BYTES>>>(data, W);
    k2_recursion<<<512, 256, SMEM2_BYTES>>>(labels, out);
    k3_dw<<<512, 256, SMEM3_BYTES>>>(data, out);
}

// round 10
// speedup vs baseline: 1.4878x; 1.1729x over previous
#include <cuda_runtime.h>

#define B_WORDS 512
#define M_POS   256
#define KK      26
#define DD      128
#define PADW    27
#define OUT_DW  (KK * DD)            // 3328
#define OUT_TOTAL (OUT_DW + KK * KK) // 4004

typedef unsigned long long ull;

// ---------- packed f32x2 helpers ----------
__device__ __forceinline__ ull pack2(float lo, float hi) {
    ull r;
    asm("mov.b64 %0, {%1,%2};" : "=l"(r) : "f"(lo), "f"(hi));
    return r;
}
__device__ __forceinline__ void unpack2(ull v, float& lo, float& hi) {
    asm("mov.b64 {%0,%1}, %2;" : "=f"(lo), "=f"(hi) : "l"(v));
}
__device__ __forceinline__ void ffma2(ull& d, ull a, ull b) {
    asm("fma.rn.f32x2 %0, %1, %2, %0;" : "+l"(d) : "l"(a), "l"(b));
}

// ---------- kernel 0: zero output ----------
__global__ void k0_init(float* __restrict__ out) {
    int i = blockIdx.x * blockDim.x + threadIdx.x;
    if (i < OUT_TOTAL) out[i] = 0.0f;
}

// ---------- mega kernel: one word per block, everything fused ----------
// Dynamic smem layout:
//   ull  region [0, 2048)         : sU  = sW2 (phase 1, 64*28 used) / sM2 (phase 4, 64*32)
//   float region (after 16384 B)  :
//     F_X   sX  [64*132]  (X chunk / final dw merge buffer)
//     F_A   sA  [256*27+8]
//     F_B   sB  [256*27+8]  (Bt; overwritten by M in phase C)
//     F_T   sT  [704]       (exp(T), zero-padded)
//     F_B0  sb0 [32]
//     F_DT  sdT [676]
//     F_LAB slab[256] (int)
#define F_X   0
#define F_A   8448
#define F_B   15368
#define F_T   22288
#define F_B0  22992
#define F_DT  23024
#define F_LAB 23700
#define F_END 23956
#define SMEM_BYTES (2048 * 8 + F_END * 4)   // 112208

__global__ void __launch_bounds__(256) mega(const float* __restrict__ X,
                                            const int* __restrict__ labels,
                                            const float* __restrict__ Wg,
                                            const float* __restrict__ Tg,
                                            float* __restrict__ out) {
    extern __shared__ ull dynU[];
    ull*   sU = dynU;                       // sW2 / sM2
    float* f  = (float*)(dynU + 2048);
    float* sX  = f + F_X;
    float* sA  = f + F_A;
    float* sB  = f + F_B;
    float* sT  = f + F_T;
    float* sb0 = f + F_B0;
    float* sdT = f + F_DT;
    int*   slab = (int*)(f + F_LAB);

    const int w    = blockIdx.x;
    const int t    = threadIdx.x;
    const int warp = t >> 5, lane = t & 31;
    const size_t rowbase = (size_t)w * M_POS;

    // ================= init staging =================
    // sW2: [s2(64)][28 slots] ull = (W[k][2s2], W[k][2s2+1]); slots 26,27 zero.
    for (int e = t; e < 64 * 28; e += 256) {
        int s2 = e / 28, slot = e - s2 * 28;
        float lo = 0.0f, hi = 0.0f;
        if (slot < KK) { lo = Wg[slot * DD + 2 * s2]; hi = Wg[slot * DD + 2 * s2 + 1]; }
        sU[e] = pack2(lo, hi);
    }
    for (int e = t; e < 704; e += 256) sT[e] = (e < KK * KK) ? __expf(Tg[e]) : 0.0f;
    for (int e = t; e < M_POS * PADW + 8; e += 256) { sA[e] = 0.0f; sB[e] = 0.0f; }
    for (int e = t; e < KK * KK; e += 256) sdT[e] = 0.0f;
    for (int e = t; e < M_POS; e += 256) slab[e] = labels[rowbase + e];
    if (t < 32) sb0[t] = 0.0f;

    // ================= phase 1: scores + es, 4 chunks of 64 rows =================
    const int p1row = t >> 2;          // 0..63
    const int kq    = t & 3;           // k-quarter: k = kq*7 + j (j<7; k>=26 are pads)
    for (int ch = 0; ch < 4; ch++) {
        const int rb = ch * 64;
        __syncthreads();
        for (int e = t; e < 2048; e += 256) {
            int r = e >> 5, q4 = e & 31;
            float4 v = ((const float4*)(X + (rowbase + rb + r) * DD))[q4];
            *(float4*)&sX[r * 132 + q4 * 4] = v;
        }
        __syncthreads();
        ull acc[7];
#pragma unroll
        for (int j = 0; j < 7; j++) acc[j] = 0ull;
        const float* xr = sX + p1row * 132;
        const ull*   wb = sU + kq * 7;
#pragma unroll 8
        for (int s2 = 0; s2 < 64; s2++) {
            ull xv = *(const ull*)&xr[2 * s2];
            const ull* wp = wb + s2 * 28;
#pragma unroll
            for (int j = 0; j < 7; j++) ffma2(acc[j], xv, wp[j]);
        }
        float sv[7];
        float mx = 0.0f;   // pads contribute 0; harmless for softmax scaling
#pragma unroll
        for (int j = 0; j < 7; j++) {
            float lo, hi; unpack2(acc[j], lo, hi);
            sv[j] = lo + hi;
            mx = fmaxf(mx, sv[j]);
        }
        mx = fmaxf(mx, __shfl_xor_sync(0xffffffffu, mx, 1));
        mx = fmaxf(mx, __shfl_xor_sync(0xffffffffu, mx, 2));
        const int ri = rb + p1row;
#pragma unroll
        for (int j = 0; j < 7; j++) {
            int k = kq * 7 + j;
            if (k < KK) {
                float v = __expf(sv[j] - mx);
                sA[ri * PADW + k] = v;
                sB[ri * PADW + k] = v;
            }
        }
    }
    __syncthreads();

    // ================= phase 2: serial recursions =================
    if (warp == 0) {
        float eTc[KK];                              // lane y: eT[:, y]
#pragma unroll
        for (int j = 0; j < KK; j++) eTc[j] = sT[j * KK + lane];
        for (int i = 1; i < M_POS; i++) {
            const float* prev = sA + (i - 1) * PADW;
            float v0 = 0.f, v1 = 0.f, v2 = 0.f, v3 = 0.f;
#pragma unroll
            for (int j = 0; j < 24; j += 4) {
                v0 = fmaf(prev[j],     eTc[j],     v0);
                v1 = fmaf(prev[j + 1], eTc[j + 1], v1);
                v2 = fmaf(prev[j + 2], eTc[j + 2], v2);
                v3 = fmaf(prev[j + 3], eTc[j + 3], v3);
            }
            v0 = fmaf(prev[24], eTc[24], v0);
            v1 = fmaf(prev[25], eTc[25], v1);
            float v  = (v0 + v1) + (v2 + v3);
            float nw = v * sA[i * PADW + lane];
            if ((i & 7) == 0) {
                float tmx = (lane < KK) ? nw : 0.0f;
#pragma unroll
                for (int o = 16; o; o >>= 1) tmx = fmaxf(tmx, __shfl_xor_sync(0xffffffffu, tmx, o));
                float sc = (tmx > 0.0f) ? __fdividef(1.0f, tmx) : 1.0f;
                nw *= sc;
            }
            if (lane < KK) sA[i * PADW + lane] = nw;
            __syncwarp();
        }
    } else if (warp == 1) {
        int ll = (lane < KK) ? lane : 0;
        float eTr[KK];                              // lane y: eT[y, :]
#pragma unroll
        for (int j = 0; j < KK; j++) eTr[j] = sT[ll * KK + j];
        for (int i = M_POS - 2; i >= 0; i--) {
            const float* nxt = sB + (i + 1) * PADW;
            float v0 = 0.f, v1 = 0.f, v2 = 0.f, v3 = 0.f;
#pragma unroll
            for (int j = 0; j < 24; j += 4) {
                v0 = fmaf(nxt[j],     eTr[j],     v0);
                v1 = fmaf(nxt[j + 1], eTr[j + 1], v1);
                v2 = fmaf(nxt[j + 2], eTr[j + 2], v2);
                v3 = fmaf(nxt[j + 3], eTr[j + 3], v3);
            }
            v0 = fmaf(nxt[24], eTr[24], v0);
            v1 = fmaf(nxt[25], eTr[25], v1);
            float v = (v0 + v1) + (v2 + v3);
            if (i == 0 && lane < KK) sb0[lane] = v;
            float nw = v * sB[i * PADW + lane];
            if ((i & 7) == 0) {
                float tmx = (lane < KK) ? nw : 0.0f;
#pragma unroll
                for (int o = 16; o; o >>= 1) tmx = fmaxf(tmx, __shfl_xor_sync(0xffffffffu, tmx, o));
                float sc = (tmx > 0.0f) ? __fdividef(1.0f, tmx) : 1.0f;
                nw *= sc;
            }
            if (lane < KK) sB[i * PADW + lane] = nw;
            __syncwarp();
        }
    } else {
        // warps 2..7: prefetch phase-4 chunk 0 of X into sX during the recursion
        for (int e = t - 64; e < 2048; e += 192) {
            int r = e >> 5, q4 = e & 31;
            float4 v = ((const float4*)(X + (rowbase + r) * DD))[q4];
            *(float4*)&sX[r * 132 + q4 * 4] = v;
        }
    }
    __syncthreads();

    // ================= phase 3: marginals -> M written in place over sB =================
    if (warp == 0) {   // p1[0] ~ A[0,k] * btilde0[k]
        float tv = (lane < KK) ? sA[lane] * sb0[lane] : 0.0f;
        float s = tv;
#pragma unroll
        for (int o = 16; o; o >>= 1) s += __shfl_xor_sync(0xffffffffu, s, o);
        float p = tv * __fdividef(1.0f, s);
        if (lane < KK) sB[lane] = ((slab[0] == lane) ? 1.0f : 0.0f) - p;
    }

    {
        float eTc[KK];   // eT[a, lane]
#pragma unroll
        for (int a = 0; a < KK; a++) eTc[a] = sT[a * KK + lane];
        float ga[KK];
#pragma unroll
        for (int a = 0; a < KK; a++) ga[a] = 0.0f;

        for (int i = warp; i < M_POS - 1; i += 8) {
            const float* Ar = sA + i * PADW;
            float wb = sB[(i + 1) * PADW + lane];
            float s0 = 0.f, s1 = 0.f;
#pragma unroll
            for (int a = 0; a < KK; a += 2) {
                s0 = fmaf(Ar[a],     eTc[a],     s0);
                s1 = fmaf(Ar[a + 1], eTc[a + 1], s1);
            }
            float sb = s0 + s1;
            float contrib = (lane < KK) ? sb * wb : 0.0f;
            float S = contrib;
#pragma unroll
            for (int o = 16; o; o >>= 1) S += __shfl_xor_sync(0xffffffffu, S, o);
            float invS = __fdividef(1.0f, S);
            float fko = wb * invS;
#pragma unroll
            for (int a = 0; a < KK; a++) ga[a] = fmaf(Ar[a], fko, ga[a]);
            int y1 = slab[i + 1];
            if (lane < KK) {
                float p = sb * fko;   // p1[i+1, lane]
                sB[(i + 1) * PADW + lane] = ((y1 == lane) ? 1.0f : 0.0f) - p;  // M[i+1]
            }
            if (lane == 0) atomicAdd(&sdT[slab[i] * KK + y1], 1.0f);
        }
#pragma unroll
        for (int a = 0; a < KK; a++)
            if (lane < KK) atomicAdd(&sdT[a * KK + lane], -eTc[a] * ga[a]);
    }
    __syncthreads();

    // dT output (mean over words)
    {
        const float invB = 1.0f / (float)B_WORDS;
        for (int e = t; e < KK * KK; e += 256)
            atomicAdd(out + OUT_DW + e, sdT[e] * invB);
    }

    // ================= phase 4: dw = M^T @ X, streaming X again =================
    const int kh = warp & 1;     // k-half
    const int rh = warp >> 1;    // row quarter within 64-row chunk
    ull accA[13], accB[13];
#pragma unroll
    for (int j = 0; j < 13; j++) { accA[j] = 0ull; accB[j] = 0ull; }

    for (int ch = 0; ch < 4; ch++) {
        const int rb = ch * 64;
        __syncthreads();
        if (ch > 0) {   // chunk 0 was prefetched during the recursion
            for (int e = t; e < 2048; e += 256) {
                int r = e >> 5, q4 = e & 31;
                float4 v = ((const float4*)(X + (rowbase + rb + r) * DD))[q4];
                *(float4*)&sX[r * 132 + q4 * 4] = v;
            }
        }
        // convert M rows (in sB) to duplicated ull: sM2[r(64)][32]; slots 0..12=k0..12, 16..28=k13..25
        for (int e = t; e < 2048; e += 256) {
            int r = e >> 5, slot = e & 31;
            int k = -1;
            if (slot < 13) k = slot;
            else if (slot >= 16 && slot < 29) k = slot - 3;
            float m = (k >= 0) ? sB[(rb + r) * PADW + k] : 0.0f;
            sU[e] = pack2(m, m);
        }
        __syncthreads();
#pragma unroll 2
        for (int rr = 0; rr < 16; rr++) {
            int r = rh * 16 + rr;
            const float* xp = sX + r * 132;
            ull xa = *(const ull*)&xp[lane * 2];
            ull xb = *(const ull*)&xp[64 + lane * 2];
            const ull* mp = sU + r * 32 + kh * 16;
            ull mv[13];
            ulonglong2 q;
            q = ((const ulonglong2*)mp)[0]; mv[0] = q.x;  mv[1] = q.y;
            q = ((const ulonglong2*)mp)[1]; mv[2] = q.x;  mv[3] = q.y;
            q = ((const ulonglong2*)mp)[2]; mv[4] = q.x;  mv[5] = q.y;
            q = ((const ulonglong2*)mp)[3]; mv[6] = q.x;  mv[7] = q.y;
            q = ((const ulonglong2*)mp)[4]; mv[8] = q.x;  mv[9] = q.y;
            q = ((const ulonglong2*)mp)[5]; mv[10] = q.x; mv[11] = q.y;
            mv[12] = mp[12];
#pragma unroll
            for (int j = 0; j < 13; j++) {
                ffma2(accA[j], mv[j], xa);
                ffma2(accB[j], mv[j], xb);
            }
        }
    }

    // merge the 4 rh partials in smem (ordered passes), then global atomics
    __syncthreads();
    float* dwS = sX;   // 3328 floats, [k(26)][d(128)]
    for (int p = 0; p < 4; p++) {
        if (rh == p) {
#pragma unroll
            for (int j = 0; j < 13; j++) {
                int k = kh * 13 + j;
                float* o = dwS + k * 128;
                float loA, hiA, loB, hiB;
                unpack2(accA[j], loA, hiA);
                unpack2(accB[j], loB, hiB);
                if (p == 0) {
                    o[lane * 2]          = loA;
                    o[lane * 2 + 1]      = hiA;
                    o[64 + lane * 2]     = loB;
                    o[64 + lane * 2 + 1] = hiB;
                } else {
                    o[lane * 2]          += loA;
                    o[lane * 2 + 1]      += hiA;
                    o[64 + lane * 2]     += loB;
                    o[64 + lane * 2 + 1] += hiB;
                }
            }
        }
        __syncthreads();
    }
    {
        const float sc = 1.0f / (float)B_WORDS;
        for (int e = t; e < OUT_DW; e += 256)
            atomicAdd(out + e, dwS[e] * sc);
    }
}

// ---------- launch ----------
extern "C" void kernel_launch(void* const* d_in, const int* in_sizes, int n_in,
                              void* d_out, int out_size) {
    const float* data   = (const float*)d_in[0];   // [512,256,128] f32
    const int*   labels = (const int*)d_in[1];     // [512,256] int32
    const float* W      = (const float*)d_in[2];   // [26,128] f32
    const float* T      = (const float*)d_in[3];   // [26,26] f32
    float* out = (float*)d_out;                    // [4004] f32

    cudaFuncSetAttribute(mega, cudaFuncAttributeMaxDynamicSharedMemorySize, SMEM_BYTES);

    k0_init<<<16, 256>>>(out);
    mega<<<B_WORDS, 256, SMEM_BYTES>>>(data, labels, W, T, out);
}

// round 11
// speedup vs baseline: 1.5272x; 1.0265x over previous
#include <cuda_runtime.h>

#define B_WORDS 512
#define M_POS   256
#define KK      26
#define DD      128
#define PADW    27
#define OUT_DW  (KK * DD)            // 3328
#define OUT_TOTAL (OUT_DW + KK * KK) // 4004

typedef unsigned long long ull;

// ---------- packed f32x2 helpers ----------
__device__ __forceinline__ ull pack2(float lo, float hi) {
    ull r;
    asm("mov.b64 %0, {%1,%2};" : "=l"(r) : "f"(lo), "f"(hi));
    return r;
}
__device__ __forceinline__ void unpack2(ull v, float& lo, float& hi) {
    asm("mov.b64 {%0,%1}, %2;" : "=f"(lo), "=f"(hi) : "l"(v));
}
__device__ __forceinline__ void ffma2(ull& d, ull a, ull b) {
    asm("fma.rn.f32x2 %0, %1, %2, %0;" : "+l"(d) : "l"(a), "l"(b));
}

// ---------- kernel 0: zero output ----------
__global__ void k0_init(float* __restrict__ out) {
    int i = blockIdx.x * blockDim.x + threadIdx.x;
    if (i < OUT_TOTAL) out[i] = 0.0f;
}

// ---------- mega kernel: one word per block, everything fused ----------
// Dynamic smem layout:
//   ull  region [0, 2048)         : sU = sW2 (phase 1, 64*28 used) / sM2 (phase 4, 64*32)
//   float region (after 16384 B)  :
//     F_X   sX  [64*132]  (X chunk / final dw merge buffer)
//     F_A   sA  [256*27+8]
//     F_B   sB  [256*27+8]  (Bt; overwritten by M in phase 3)
//     F_T   sT  [704]       (exp(T), zero-padded)
//     F_B0  sb0 [32]
//     F_DT  sdT [676]
//     F_LAB slab[256] (int)
#define F_X   0
#define F_A   8448
#define F_B   15368
#define F_T   22288
#define F_B0  22992
#define F_DT  23024
#define F_LAB 23700
#define F_END 23956
#define SMEM_BYTES (2048 * 8 + F_END * 4)   // 112208

__global__ void __launch_bounds__(256) mega(const float* __restrict__ X,
                                            const int* __restrict__ labels,
                                            const float* __restrict__ Wg,
                                            const float* __restrict__ Tg,
                                            float* __restrict__ out) {
    extern __shared__ ull dynU[];
    ull*   sU = dynU;                       // sW2 / sM2
    float* f  = (float*)(dynU + 2048);
    float* sX  = f + F_X;
    float* sA  = f + F_A;
    float* sB  = f + F_B;
    float* sT  = f + F_T;
    float* sb0 = f + F_B0;
    float* sdT = f + F_DT;
    int*   slab = (int*)(f + F_LAB);

    const int w    = blockIdx.x;
    const int t    = threadIdx.x;
    const int warp = t >> 5, lane = t & 31;
    const size_t rowbase = (size_t)w * M_POS;

    // ================= init staging =================
    // sW2: [s2(64)][28 slots] ull = (W[k][2s2], W[k][2s2+1]);
    // slots 0..12 = k 0..12, slots 14..26 = k 13..25 (13,27 zero) -> 16B-aligned halves.
    for (int e = t; e < 64 * 28; e += 256) {
        int s2 = e / 28, slot = e - s2 * 28;
        float lo = 0.0f, hi = 0.0f;
        int k = -1;
        if (slot < 13) k = slot;
        else if (slot >= 14 && slot < 27) k = slot - 1;
        if (k >= 0) { lo = Wg[k * DD + 2 * s2]; hi = Wg[k * DD + 2 * s2 + 1]; }
        sU[e] = pack2(lo, hi);
    }
    for (int e = t; e < 704; e += 256) sT[e] = (e < KK * KK) ? __expf(Tg[e]) : 0.0f;
    for (int e = t; e < M_POS * PADW + 8; e += 256) { sA[e] = 0.0f; sB[e] = 0.0f; }
    for (int e = t; e < KK * KK; e += 256) sdT[e] = 0.0f;
    for (int e = t; e < M_POS; e += 256) slab[e] = labels[rowbase + e];
    if (t < 32) sb0[t] = 0.0f;

    // ================= phase 1: scores + es, 4 chunks of 64 rows =================
    // thread = (row = t>>2, khp = (t>>1)&1, dh = t&1). 13 k x 32 interleaved d-pairs.
    {
        const int dh  = t & 1;
        const int khp = (t >> 1) & 1;
        const int row = t >> 2;          // 0..63
        for (int ch = 0; ch < 4; ch++) {
            const int rb = ch * 64;
            __syncthreads();
            for (int e = t; e < 2048; e += 256) {
                int r = e >> 5, q4 = e & 31;
                float4 v = ((const float4*)(X + (rowbase + rb + r) * DD))[q4];
                *(float4*)&sX[r * 132 + q4 * 4] = v;
            }
            __syncthreads();
            ull acc[13];
#pragma unroll
            for (int j = 0; j < 13; j++) acc[j] = 0ull;
            const float* xr = sX + row * 132 + 2 * dh;   // d-pair = 2s + dh
            const ull*   wb = sU + khp * 14 + dh * 28;   // step stride 56 ull
#pragma unroll 4
            for (int s = 0; s < 32; s++) {
                ull xv = *(const ull*)&xr[4 * s];
                const ull* wp = wb + 56 * s;
                ull wv[13];
                ulonglong2 q;
                q = ((const ulonglong2*)wp)[0]; wv[0] = q.x;  wv[1] = q.y;
                q = ((const ulonglong2*)wp)[1]; wv[2] = q.x;  wv[3] = q.y;
                q = ((const ulonglong2*)wp)[2]; wv[4] = q.x;  wv[5] = q.y;
                q = ((const ulonglong2*)wp)[3]; wv[6] = q.x;  wv[7] = q.y;
                q = ((const ulonglong2*)wp)[4]; wv[8] = q.x;  wv[9] = q.y;
                q = ((const ulonglong2*)wp)[5]; wv[10] = q.x; wv[11] = q.y;
                wv[12] = wp[12];
#pragma unroll
                for (int j = 0; j < 13; j++) ffma2(acc[j], xv, wv[j]);
            }
            // reduce across dh (lane^1), max across khp (lane^2)
            float sv[13];
            float mx;
#pragma unroll
            for (int j = 0; j < 13; j++) {
                float lo, hi; unpack2(acc[j], lo, hi);
                sv[j] = lo + hi;
            }
#pragma unroll
            for (int j = 0; j < 13; j++)
                sv[j] += __shfl_xor_sync(0xffffffffu, sv[j], 1);
            mx = sv[0];
#pragma unroll
            for (int j = 1; j < 13; j++) mx = fmaxf(mx, sv[j]);
            mx = fmaxf(mx, __shfl_xor_sync(0xffffffffu, mx, 2));
            const int ri = rb + row;
            const int j0 = dh ? 7 : 0, j1 = dh ? 13 : 7;
#pragma unroll
            for (int j = 0; j < 13; j++) {
                if (j >= j0 && j < j1) {
                    int k = khp * 13 + j;
                    float v = __expf(sv[j] - mx);
                    sA[ri * PADW + k] = v;
                    sB[ri * PADW + k] = v;
                }
            }
        }
    }
    __syncthreads();

    // ================= phase 2: serial recursions =================
    if (warp == 0) {
        float eTc[KK];                              // lane y: eT[:, y]
#pragma unroll
        for (int j = 0; j < KK; j++) eTc[j] = sT[j * KK + lane];
        for (int i = 1; i < M_POS; i++) {
            const float* prev = sA + (i - 1) * PADW;
            float v0 = 0.f, v1 = 0.f, v2 = 0.f, v3 = 0.f;
#pragma unroll
            for (int j = 0; j < 24; j += 4) {
                v0 = fmaf(prev[j],     eTc[j],     v0);
                v1 = fmaf(prev[j + 1], eTc[j + 1], v1);
                v2 = fmaf(prev[j + 2], eTc[j + 2], v2);
                v3 = fmaf(prev[j + 3], eTc[j + 3], v3);
            }
            v0 = fmaf(prev[24], eTc[24], v0);
            v1 = fmaf(prev[25], eTc[25], v1);
            float v  = (v0 + v1) + (v2 + v3);
            float nw = v * sA[i * PADW + lane];
            if ((i & 7) == 0) {
                float tmx = (lane < KK) ? nw : 0.0f;
#pragma unroll
                for (int o = 16; o; o >>= 1) tmx = fmaxf(tmx, __shfl_xor_sync(0xffffffffu, tmx, o));
                float sc = (tmx > 0.0f) ? __fdividef(1.0f, tmx) : 1.0f;
                nw *= sc;
            }
            if (lane < KK) sA[i * PADW + lane] = nw;
            __syncwarp();
        }
    } else if (warp == 1) {
        int ll = (lane < KK) ? lane : 0;
        float eTr[KK];                              // lane y: eT[y, :]
#pragma unroll
        for (int j = 0; j < KK; j++) eTr[j] = sT[ll * KK + j];
        for (int i = M_POS - 2; i >= 0; i--) {
            const float* nxt = sB + (i + 1) * PADW;
            float v0 = 0.f, v1 = 0.f, v2 = 0.f, v3 = 0.f;
#pragma unroll
            for (int j = 0; j < 24; j += 4) {
                v0 = fmaf(nxt[j],     eTr[j],     v0);
                v1 = fmaf(nxt[j + 1], eTr[j + 1], v1);
                v2 = fmaf(nxt[j + 2], eTr[j + 2], v2);
                v3 = fmaf(nxt[j + 3], eTr[j + 3], v3);
            }
            v0 = fmaf(nxt[24], eTr[24], v0);
            v1 = fmaf(nxt[25], eTr[25], v1);
            float v = (v0 + v1) + (v2 + v3);
            if (i == 0 && lane < KK) sb0[lane] = v;
            float nw = v * sB[i * PADW + lane];
            if ((i & 7) == 0) {
                float tmx = (lane < KK) ? nw : 0.0f;
#pragma unroll
                for (int o = 16; o; o >>= 1) tmx = fmaxf(tmx, __shfl_xor_sync(0xffffffffu, tmx, o));
                float sc = (tmx > 0.0f) ? __fdividef(1.0f, tmx) : 1.0f;
                nw *= sc;
            }
            if (lane < KK) sB[i * PADW + lane] = nw;
            __syncwarp();
        }
    } else {
        // warps 2..7: prefetch phase-4 chunk 0 of X into sX during the recursion
        for (int e = t - 64; e < 2048; e += 192) {
            int r = e >> 5, q4 = e & 31;
            float4 v = ((const float4*)(X + (rowbase + r) * DD))[q4];
            *(float4*)&sX[r * 132 + q4 * 4] = v;
        }
    }
    __syncthreads();

    // ================= phase 3: marginals -> M written in place over sB =================
    if (warp == 0) {   // p1[0] ~ A[0,k] * btilde0[k]
        float tv = (lane < KK) ? sA[lane] * sb0[lane] : 0.0f;
        float s = tv;
#pragma unroll
        for (int o = 16; o; o >>= 1) s += __shfl_xor_sync(0xffffffffu, s, o);
        float p = tv * __fdividef(1.0f, s);
        if (lane < KK) sB[lane] = ((slab[0] == lane) ? 1.0f : 0.0f) - p;
    }

    {
        float eTc[KK];   // eT[a, lane]
#pragma unroll
        for (int a = 0; a < KK; a++) eTc[a] = sT[a * KK + lane];
        float ga[KK];
#pragma unroll
        for (int a = 0; a < KK; a++) ga[a] = 0.0f;

        for (int i = warp; i < M_POS - 1; i += 8) {
            const float* Ar = sA + i * PADW;
            float wb = sB[(i + 1) * PADW + lane];
            float s0 = 0.f, s1 = 0.f;
#pragma unroll
            for (int a = 0; a < KK; a += 2) {
                s0 = fmaf(Ar[a],     eTc[a],     s0);
                s1 = fmaf(Ar[a + 1], eTc[a + 1], s1);
            }
            float sb = s0 + s1;
            float contrib = (lane < KK) ? sb * wb : 0.0f;
            float S = contrib;
#pragma unroll
            for (int o = 16; o; o >>= 1) S += __shfl_xor_sync(0xffffffffu, S, o);
            float invS = __fdividef(1.0f, S);
            float fko = wb * invS;
#pragma unroll
            for (int a = 0; a < KK; a++) ga[a] = fmaf(Ar[a], fko, ga[a]);
            int y1 = slab[i + 1];
            if (lane < KK) {
                float p = sb * fko;   // p1[i+1, lane]
                sB[(i + 1) * PADW + lane] = ((y1 == lane) ? 1.0f : 0.0f) - p;  // M[i+1]
            }
            if (lane == 0) atomicAdd(&sdT[slab[i] * KK + y1], 1.0f);
        }
#pragma unroll
        for (int a = 0; a < KK; a++)
            if (lane < KK) atomicAdd(&sdT[a * KK + lane], -eTc[a] * ga[a]);
    }
    __syncthreads();

    // dT output (mean over words)
    {
        const float invB = 1.0f / (float)B_WORDS;
        for (int e = t; e < KK * KK; e += 256)
            atomicAdd(out + OUT_DW + e, sdT[e] * invB);
    }

    // ================= phase 4: dw = M^T @ X, streaming X again =================
    const int kh = warp & 1;     // k-half
    const int rh = warp >> 1;    // row quarter within 64-row chunk
    ull accA[13], accB[13];
#pragma unroll
    for (int j = 0; j < 13; j++) { accA[j] = 0ull; accB[j] = 0ull; }

    for (int ch = 0; ch < 4; ch++) {
        const int rb = ch * 64;
        __syncthreads();
        if (ch > 0) {   // chunk 0 was prefetched during the recursion
            for (int e = t; e < 2048; e += 256) {
                int r = e >> 5, q4 = e & 31;
                float4 v = ((const float4*)(X + (rowbase + rb + r) * DD))[q4];
                *(float4*)&sX[r * 132 + q4 * 4] = v;
            }
        }
        // convert M rows (in sB) to duplicated ull: sM2[r(64)][32]; slots 0..12=k0..12, 16..28=k13..25
        for (int e = t; e < 2048; e += 256) {
            int r = e >> 5, slot = e & 31;
            int k = -1;
            if (slot < 13) k = slot;
            else if (slot >= 16 && slot < 29) k = slot - 3;
            float m = (k >= 0) ? sB[(rb + r) * PADW + k] : 0.0f;
            sU[e] = pack2(m, m);
        }
        __syncthreads();
#pragma unroll 2
        for (int rr = 0; rr < 16; rr++) {
            int r = rh * 16 + rr;
            const float* xp = sX + r * 132;
            ull xa = *(const ull*)&xp[lane * 2];
            ull xb = *(const ull*)&xp[64 + lane * 2];
            const ull* mp = sU + r * 32 + kh * 16;
            ull mv[13];
            ulonglong2 q;
            q = ((const ulonglong2*)mp)[0]; mv[0] = q.x;  mv[1] = q.y;
            q = ((const ulonglong2*)mp)[1]; mv[2] = q.x;  mv[3] = q.y;
            q = ((const ulonglong2*)mp)[2]; mv[4] = q.x;  mv[5] = q.y;
            q = ((const ulonglong2*)mp)[3]; mv[6] = q.x;  mv[7] = q.y;
            q = ((const ulonglong2*)mp)[4]; mv[8] = q.x;  mv[9] = q.y;
            q = ((const ulonglong2*)mp)[5]; mv[10] = q.x; mv[11] = q.y;
            mv[12] = mp[12];
#pragma unroll
            for (int j = 0; j < 13; j++) {
                ffma2(accA[j], mv[j], xa);
                ffma2(accB[j], mv[j], xb);
            }
        }
    }

    // merge the 4 rh partials in smem (ordered passes), then global atomics
    __syncthreads();
    float* dwS = sX;   // 3328 floats, [k(26)][d(128)]
    for (int p = 0; p < 4; p++) {
        if (rh == p) {
#pragma unroll
            for (int j = 0; j < 13; j++) {
                int k = kh * 13 + j;
                float* o = dwS + k * 128;
                float loA, hiA, loB, hiB;
                unpack2(accA[j], loA, hiA);
                unpack2(accB[j], loB, hiB);
                if (p == 0) {
                    o[lane * 2]          = loA;
                    o[lane * 2 + 1]      = hiA;
                    o[64 + lane * 2]     = loB;
                    o[64 + lane * 2 + 1] = hiB;
                } else {
                    o[lane * 2]          += loA;
                    o[lane * 2 + 1]      += hiA;
                    o[64 + lane * 2]     += loB;
                    o[64 + lane * 2 + 1] += hiB;
                }
            }
        }
        __syncthreads();
    }
    {
        const float sc = 1.0f / (float)B_WORDS;
        for (int e = t; e < OUT_DW; e += 256)
            atomicAdd(out + e, dwS[e] * sc);
    }
}

// ---------- launch ----------
extern "C" void kernel_launch(void* const* d_in, const int* in_sizes, int n_in,
                              void* d_out, int out_size) {
    const float* data   = (const float*)d_in[0];   // [512,256,128] f32
    const int*   labels = (const int*)d_in[1];     // [512,256] int32
    const float* W      = (const float*)d_in[2];   // [26,128] f32
    const float* T      = (const float*)d_in[3];   // [26,26] f32
    float* out = (float*)d_out;                    // [4004] f32

    cudaFuncSetAttribute(mega, cudaFuncAttributeMaxDynamicSharedMemorySize, SMEM_BYTES);

    k0_init<<<16, 256>>>(out);
    mega<<<B_WORDS, 256, SMEM_BYTES>>>(data, labels, W, T, out);
}